// round 16
// baseline (speedup 1.0000x reference)
#include <cuda_runtime.h>
#include <cuda_fp16.h>
#include <cstdint>

#define BSZ 2
#define NH 16
#define SEQ 2048
#define DM 1024
#define HD 64
#define BH (BSZ*NH)

// Scratch (device globals — no allocations allowed)
__device__ __half g_x16[BSZ*SEQ*DM];    // x (fp16)
__device__ __half g_w16[3*DM*DM];       // W (fp16)
__device__ __half g_q16[BH * SEQ * HD]; // q pre-scaled by 0.125*log2(e)
__device__ __half g_k16[BH * SEQ * HD];
__device__ __half g_v16[BH * SEQ * HD];
__device__ __half g_bmh[(size_t)NH * SEQ * SEQ];   // premasked bias*log2e (fp16)

#define LOG2E 1.44269504f
#define QSCALE (0.125f * LOG2E)
#define ONES2  0x3C003C00u      // half2(1.0, 1.0)
#define MASKV  (-60000.0f)      // fp16-safe "minus infinity" (ex2 -> 0)

// ---- helpers -----------------------------------------------------------------
__device__ __forceinline__ uint32_t h2bits(__half2 v) {
    return *reinterpret_cast<uint32_t*>(&v);
}
__device__ __forceinline__ float ex2(float x) {
    float y; asm("ex2.approx.ftz.f32 %0, %1;" : "=f"(y) : "f"(x)); return y;
}
__device__ __forceinline__ uint32_t smem_u32(const void* p) {
    uint32_t a;
    asm("{ .reg .u64 t; cvta.to.shared.u64 t, %1; cvt.u32.u64 %0, t; }"
        : "=r"(a) : "l"(p));
    return a;
}
// 128B-row tiles: XOR 16B-chunk by (row&7)
__device__ __forceinline__ uint32_t swz_addr(uint32_t base, int row, int chunk) {
    uint32_t off = (uint32_t)(row * 128 + chunk * 16);
    return base + (off ^ ((off >> 3) & 0x70));
}
// 64B-row tiles: SW64 swizzle
__device__ __forceinline__ uint32_t swz64_addr(uint32_t base, int row, int chunk) {
    uint32_t off = (uint32_t)(row * 64 + chunk * 16);
    return base + (off ^ ((off >> 3) & 0x30));
}
__device__ __forceinline__ void ldsm_x4(uint32_t* r, uint32_t a) {
    asm volatile("ldmatrix.sync.aligned.m8n8.x4.shared.b16 {%0,%1,%2,%3}, [%4];"
        : "=r"(r[0]), "=r"(r[1]), "=r"(r[2]), "=r"(r[3]) : "r"(a));
}
__device__ __forceinline__ void ldsm_x4t(uint32_t* r, uint32_t a) {
    asm volatile("ldmatrix.sync.aligned.m8n8.x4.trans.shared.b16 {%0,%1,%2,%3}, [%4];"
        : "=r"(r[0]), "=r"(r[1]), "=r"(r[2]), "=r"(r[3]) : "r"(a));
}
__device__ __forceinline__ void mma_f16(float* d, const uint32_t* a,
                                        uint32_t b0, uint32_t b1) {
    asm volatile("mma.sync.aligned.m16n8k16.row.col.f32.f16.f16.f32 "
        "{%0,%1,%2,%3}, {%4,%5,%6,%7}, {%8,%9}, {%0,%1,%2,%3};"
        : "+f"(d[0]), "+f"(d[1]), "+f"(d[2]), "+f"(d[3])
        : "r"(a[0]), "r"(a[1]), "r"(a[2]), "r"(a[3]), "r"(b0), "r"(b1));
}
__device__ __forceinline__ void cp16(uint32_t dst, const void* src) {
    asm volatile("cp.async.cg.shared.global [%0], [%1], 16;"
                 :: "r"(dst), "l"(src) : "memory");
}
#define CP_COMMIT() asm volatile("cp.async.commit_group;" ::: "memory")
#define CP_WAIT1()  asm volatile("cp.async.wait_group 1;" ::: "memory")

// ---------------------------------------------------------------------------
// Kernel 0a: round x and W to fp16.
// ---------------------------------------------------------------------------
__global__ __launch_bounds__(256) void split_src_kernel(
    const float* __restrict__ x,
    const float* __restrict__ wq, const float* __restrict__ wk,
    const float* __restrict__ wv)
{
    const int z = blockIdx.y;
    const float* src = (z == 0) ? x : (z == 1) ? wq : (z == 2) ? wk : wv;
    uint32_t* dst = (z == 0) ? (uint32_t*)g_x16
                             : (uint32_t*)(g_w16 + (size_t)(z - 1) * DM * DM);
    const size_t n2 = (z == 0) ? (size_t)BSZ * SEQ * DM / 2
                               : (size_t)DM * DM / 2;
    for (size_t i = (size_t)blockIdx.x * 256 + threadIdx.x; i < n2;
         i += (size_t)gridDim.x * 256) {
        float2 v = ((const float2*)src)[i];
        dst[i] = h2bits(__floats2half2_rn(v.x, v.y));
    }
}

// ---------------------------------------------------------------------------
// Kernel 0b: premask + prescale bias to fp16: bm = mask ? bias*log2e : -60000.
// ---------------------------------------------------------------------------
__global__ __launch_bounds__(256) void prep_bias_kernel(
    const float* __restrict__ bias, const int* __restrict__ mask)
{
    const size_t i = (size_t)blockIdx.x * 256 + threadIdx.x;  // over SEQ*SEQ/2
    int2 m = ((const int2*)mask)[i];
    #pragma unroll 4
    for (int h = 0; h < NH; h++) {
        float2 bv = ((const float2*)(bias + (size_t)h * SEQ * SEQ))[i];
        float ox = m.x ? bv.x * LOG2E : MASKV;
        float oy = m.y ? bv.y * LOG2E : MASKV;
        ((uint32_t*)(g_bmh + (size_t)h * SEQ * SEQ))[i] =
            h2bits(__floats2half2_rn(ox, oy));
    }
}

// ---------------------------------------------------------------------------
// Kernel 1: QKV projection via single-term fp16 HMMA.
// 128x128 tile, K-slab 32, 64B-row smem (SW64), double-buffered, 2 CTAs/SM.
// Q output pre-scaled by 0.125*log2e.
// ---------------------------------------------------------------------------
#define QKV_SMEM_BYTES 32768     // 2 stages x (x 8K | w 8K)

__global__ __launch_bounds__(256, 2) void qkv_hmma_kernel(
    const float* __restrict__ bq, const float* __restrict__ bk,
    const float* __restrict__ bv)
{
    extern __shared__ char smem[];
    const uint32_t sb = smem_u32(smem);
    const int tid = threadIdx.x, wid = tid >> 5, lane = tid & 31;
    const int z = blockIdx.z;
    const float* bvec = (z == 0) ? bq : (z == 1) ? bk : bv;
    __half* outp = (z == 0) ? g_q16 : (z == 1) ? g_k16 : g_v16;
    const __half* W = g_w16 + (size_t)z * DM * DM;
    const float oscale = (z == 0) ? QSCALE : 1.0f;
    const int col0 = blockIdx.x << 7;
    const int row0 = blockIdx.y << 7;

    auto issue = [&](int slab, int buf) {
        const int k0 = slab << 5;
        const uint32_t base = sb + (uint32_t)buf * 16384;
        #pragma unroll
        for (int it = 0; it < 2; it++) {
            const int idx = tid + it * 256;     // 0..511
            const int r = idx >> 2, c = idx & 3;
            uint32_t off = (uint32_t)(r * 64 + c * 16);
            off ^= (off >> 3) & 0x30;
            const size_t gx = (size_t)(row0 + r) * DM + k0 + c * 8;
            const size_t gw = (size_t)(col0 + r) * DM + k0 + c * 8;
            cp16(base + off,        g_x16 + gx);
            cp16(base + 8192 + off, W + gw);
        }
    };

    float s[16][4];
    #pragma unroll
    for (int g = 0; g < 16; g++)
        #pragma unroll
        for (int j = 0; j < 4; j++) s[g][j] = 0.0f;

    issue(0, 0);
    CP_COMMIT();

    for (int kt = 0; kt < 32; kt++) {
        if (kt) __syncthreads();
        if (kt < 31) issue(kt + 1, (kt + 1) & 1);
        CP_COMMIT();
        CP_WAIT1();
        __syncthreads();

        const uint32_t base = sb + (uint32_t)(kt & 1) * 16384;
        const int rA = (wid << 4) + (lane & 7) + ((lane >> 3) & 1) * 8;
        uint32_t ah[2][4];
        #pragma unroll
        for (int ks = 0; ks < 2; ks++) {
            const int ch = ks * 2 + (lane >> 4);
            ldsm_x4(ah[ks], swz64_addr(base, rA, ch));
        }
        #pragma unroll
        for (int nf = 0; nf < 8; nf++) {
            const int rB = nf * 16 + (lane & 7) + (lane >> 4) * 8;
            #pragma unroll
            for (int ks = 0; ks < 2; ks++) {
                const int ch = ks * 2 + ((lane >> 3) & 1);
                uint32_t w4[4];
                ldsm_x4(w4, swz64_addr(base + 8192, rB, ch));
                mma_f16(s[2*nf],   ah[ks], w4[0], w4[1]);
                mma_f16(s[2*nf+1], ah[ks], w4[2], w4[3]);
            }
        }
    }

    // epilogue: + bias (then optional q pre-scale); store fp16, head-split
    const int r1 = row0 + (wid << 4) + (lane >> 2);
    const int r2 = r1 + 8;
    const int bb1 = r1 >> 11, ss1 = r1 & (SEQ - 1);
    const int bb2 = r2 >> 11, ss2 = r2 & (SEQ - 1);
    #pragma unroll
    for (int g = 0; g < 16; g++) {
        const int c = col0 + g * 8 + (lane & 3) * 2;
        const int h = c >> 6, d = c & 63;
        float2 b2 = *(const float2*)(bvec + c);
        const size_t e1 = (((size_t)bb1 * NH + h) * SEQ + ss1) * HD + d;
        const size_t e2 = (((size_t)bb2 * NH + h) * SEQ + ss2) * HD + d;
        *(uint32_t*)&outp[e1] = h2bits(__floats2half2_rn(
            (s[g][0] + b2.x) * oscale, (s[g][1] + b2.y) * oscale));
        *(uint32_t*)&outp[e2] = h2bits(__floats2half2_rn(
            (s[g][2] + b2.x) * oscale, (s[g][3] + b2.y) * oscale));
    }
}

// ---------------------------------------------------------------------------
// Kernel 2: two-pass fp16 HMMA attention (no P scratch, no rescale pass).
// Pass A: rowsum only (S-MMA, p = ex2(s+bm), ones-MMA). li = -log2(rowsum).
// Pass B: p_norm = ex2(s + li + bm) -> coalesced fp32 attn (via swizzled
// fp16 smem stage) + PV on normalized frags -> O needs no divide.
// bm pipelined via cp.async (144B padded rows). blockIdx.y = h*2 + b.
// ---------------------------------------------------------------------------
#define SM_Q  0
#define SM_P  16384
#define SM_ST 32768
#define STAGE_BYTES 34816      // K 8192 | V 8192 | BM 18432 (128 rows x 144B)
#define BM_OFF 16384
#define ATTN_SMEM_BYTES (32768 + 2*34816)

__global__ __launch_bounds__(256, 2) void attn_mma_kernel(
    float* __restrict__ outp,
    float* __restrict__ attn)
{
    extern __shared__ char smem[];
    const uint32_t sb = smem_u32(smem);

    const int tid = threadIdx.x;
    const int wid = tid >> 5, lane = tid & 31;
    const int h  = blockIdx.y >> 1;            // bias row set
    const int b  = blockIdx.y & 1;             // batch
    const int bh = b * NH + h;
    const int q0 = blockIdx.x << 7;
    const size_t bhbase = (size_t)bh * SEQ;
    const __half* bmbase = g_bmh + ((size_t)h * SEQ + q0) * SEQ;

    // loadV=false in pass A (no PV there)
    auto issue_kv = [&](int kt, int buf, bool loadV) {
        const int k0 = kt << 6;
        const uint32_t base = sb + SM_ST + (uint32_t)buf * STAGE_BYTES;
        const char* kk = (const char*)(g_k16 + (bhbase + k0) * HD);
        const char* vv = (const char*)(g_v16 + (bhbase + k0) * HD);
        #pragma unroll
        for (int it = 0; it < 2; it++) {
            const int idx = tid + it * 256;     // 0..511
            const uint32_t off = (uint32_t)(idx << 4);
            const uint32_t dst = off ^ ((off >> 3) & 0x70);
            cp16(base + dst, kk + off);
            if (loadV) cp16(base + 8192 + dst, vv + off);
        }
        // bm block: 128 q-rows x 64 k (fp16), 8 chunks/row, 144B row stride
        #pragma unroll
        for (int it = 0; it < 4; it++) {
            const int idx = tid + it * 256;     // 0..1023
            const int r = idx >> 3, c = idx & 7;
            cp16(base + BM_OFF + (uint32_t)(r * 144 + c * 16),
                 bmbase + (size_t)r * SEQ + k0 + c * 8);
        }
    };

    // prologue: Q tile (128x64 fp16 = 16KB) + stage(0) for pass A
    {
        const char* qq = (const char*)(g_q16 + (bhbase + q0) * HD);
        #pragma unroll
        for (int it = 0; it < 4; it++) {
            const int idx = tid + it * 256;     // 0..1023
            const uint32_t off = (uint32_t)(idx << 4);
            const uint32_t dst = off ^ ((off >> 3) & 0x70);
            cp16(sb + SM_Q + dst, qq + off);
        }
    }
    issue_kv(0, 0, false);
    CP_COMMIT();

    const int r1 = (wid << 4) + (lane >> 2);
    const int qg1 = q0 + r1, qg2 = qg1 + 8;
    const int rA = (wid << 4) + (lane & 7) + ((lane >> 3) & 1) * 8;
    const int bmo1 = r1 * 144 + (lane & 3) * 4;        // byte offsets in bm block
    const int bmo2 = (r1 + 8) * 144 + (lane & 3) * 4;
    // P staging: XOR-swizzled 128B rows
    const int psw = (lane >> 2) & 7;
    const uint32_t po1 = (uint32_t)(SM_P + r1 * 128 + (lane & 3) * 4);
    const uint32_t po2 = po1 + 8 * 128;

    float racc[4] = {0.0f, 0.0f, 0.0f, 0.0f};   // ones-MMA rowsum accumulator

    // ================= Pass A: rowsums =================
    for (int kt = 0; kt < SEQ / 64; kt++) {
        if (kt) __syncthreads();
        if (kt < SEQ / 64 - 1) issue_kv(kt + 1, (kt + 1) & 1, false);
        CP_COMMIT();
        CP_WAIT1();
        __syncthreads();

        const uint32_t base = sb + SM_ST + (uint32_t)(kt & 1) * STAGE_BYTES;
        const char* bmst = smem + SM_ST + (size_t)(kt & 1) * STAGE_BYTES + BM_OFF;

        float s[8][4];
        #pragma unroll
        for (int g = 0; g < 8; g++)
            #pragma unroll
            for (int j = 0; j < 4; j++) s[g][j] = 0.0f;

        #pragma unroll
        for (int ks = 0; ks < 4; ks++) {
            uint32_t qf[4];
            ldsm_x4(qf, swz_addr(sb + SM_Q, rA, ks * 2 + (lane >> 4)));
            #pragma unroll
            for (int nf = 0; nf < 4; nf++) {
                const int rB = nf * 16 + (lane & 7) + (lane >> 4) * 8;
                uint32_t k4[4];
                ldsm_x4(k4, swz_addr(base, rB, ks * 2 + ((lane >> 3) & 1)));
                mma_f16(s[2*nf],   qf, k4[0], k4[1]);
                mma_f16(s[2*nf+1], qf, k4[2], k4[3]);
            }
        }

        uint32_t ph[4][4];
        #pragma unroll
        for (int g = 0; g < 8; g++) {
            float2 bA = __half22float2(*(const __half2*)(bmst + bmo1 + g * 16));
            float2 bB = __half22float2(*(const __half2*)(bmst + bmo2 + g * 16));
            const int ks = g >> 1, ix = (g & 1) * 2;
            ph[ks][ix + 0] = h2bits(__floats2half2_rn(ex2(s[g][0] + bA.x),
                                                      ex2(s[g][1] + bA.y)));
            ph[ks][ix + 1] = h2bits(__floats2half2_rn(ex2(s[g][2] + bB.x),
                                                      ex2(s[g][3] + bB.y)));
        }
        #pragma unroll
        for (int ks = 0; ks < 4; ks++)
            mma_f16(racc, ph[ks], ONES2, ONES2);
    }

    const float li1 = -__log2f(racc[0]);
    const float li2 = -__log2f(racc[2]);

    float o[8][4];
    #pragma unroll
    for (int g = 0; g < 8; g++)
        #pragma unroll
        for (int j = 0; j < 4; j++) o[g][j] = 0.0f;

    // ================= Pass B: normalized P + PV + attn =================
    __syncthreads();                       // all pass-A stage reads complete
    issue_kv(0, 0, true);
    CP_COMMIT();

    for (int kt = 0; kt < SEQ / 64; kt++) {
        const int k0 = kt << 6;
        if (kt) __syncthreads();
        if (kt < SEQ / 64 - 1) issue_kv(kt + 1, (kt + 1) & 1, true);
        CP_COMMIT();
        CP_WAIT1();
        __syncthreads();

        const uint32_t base = sb + SM_ST + (uint32_t)(kt & 1) * STAGE_BYTES;
        const char* bmst = smem + SM_ST + (size_t)(kt & 1) * STAGE_BYTES + BM_OFF;

        float s[8][4];
        #pragma unroll
        for (int g = 0; g < 8; g++)
            #pragma unroll
            for (int j = 0; j < 4; j++) s[g][j] = 0.0f;

        #pragma unroll
        for (int ks = 0; ks < 4; ks++) {
            uint32_t qf[4];
            ldsm_x4(qf, swz_addr(sb + SM_Q, rA, ks * 2 + (lane >> 4)));
            #pragma unroll
            for (int nf = 0; nf < 4; nf++) {
                const int rB = nf * 16 + (lane & 7) + (lane >> 4) * 8;
                uint32_t k4[4];
                ldsm_x4(k4, swz_addr(base, rB, ks * 2 + ((lane >> 3) & 1)));
                mma_f16(s[2*nf],   qf, k4[0], k4[1]);
                mma_f16(s[2*nf+1], qf, k4[2], k4[3]);
            }
        }

        // epilogue: p_norm = ex2(s + li + bm); normalized fp16 P -> smem + frags
        uint32_t ph[4][4];
        #pragma unroll
        for (int g = 0; g < 8; g++) {
            float2 bA = __half22float2(*(const __half2*)(bmst + bmo1 + g * 16));
            float2 bB = __half22float2(*(const __half2*)(bmst + bmo2 + g * 16));
            float p0 = ex2((s[g][0] + li1) + bA.x);
            float p1 = ex2((s[g][1] + li1) + bA.y);
            float p2 = ex2((s[g][2] + li2) + bB.x);
            float p3 = ex2((s[g][3] + li2) + bB.y);
            const uint32_t h01 = h2bits(__floats2half2_rn(p0, p1));
            const uint32_t h23 = h2bits(__floats2half2_rn(p2, p3));
            const uint32_t go = (uint32_t)((g ^ psw) << 4);
            *(uint32_t*)(smem + po1 + go) = h01;
            *(uint32_t*)(smem + po2 + go) = h23;
            const int ks = g >> 1, ix = (g & 1) * 2;
            ph[ks][ix + 0] = h01;
            ph[ks][ix + 1] = h23;
        }

        // O += P_norm V (tensor pipe)
        #pragma unroll
        for (int ks = 0; ks < 4; ks++) {
            const int rV = ks * 16 + (lane & 7) + ((lane >> 3) & 1) * 8;
            #pragma unroll
            for (int dg = 0; dg < 4; dg++) {
                uint32_t v4[4];
                ldsm_x4t(v4, swz_addr(base + 8192, rV, 2 * dg + (lane >> 4)));
                mma_f16(o[2*dg],   ph[ks], v4[0], v4[1]);
                mma_f16(o[2*dg+1], ph[ks], v4[2], v4[3]);
            }
        }

        // expand P tile (fp16 smem) -> coalesced fp32 attn stores
        __syncthreads();
        #pragma unroll
        for (int it = 0; it < 4; it++) {
            const int idx = tid + it * 256;    // 0..1023 chunks of 16B
            const int r = idx >> 3, c = idx & 7;
            uint4 hv = *(const uint4*)(smem + SM_P + r * 128 + ((c ^ (r & 7)) << 4));
            const __half2* hp = (const __half2*)&hv;
            float2 f0 = __half22float2(hp[0]);
            float2 f1 = __half22float2(hp[1]);
            float2 f2 = __half22float2(hp[2]);
            float2 f3 = __half22float2(hp[3]);
            float4* dst = (float4*)(attn + (bhbase + q0 + r) * SEQ + k0 + c * 8);
            dst[0] = make_float4(f0.x, f0.y, f1.x, f1.y);
            dst[1] = make_float4(f2.x, f2.y, f3.x, f3.y);
        }
    }

    // O is already normalized
    float* or1 = outp + (bhbase + qg1) * HD;
    float* or2 = outp + (bhbase + qg2) * HD;
    #pragma unroll
    for (int g = 0; g < 8; g++) {
        const int c = g * 8 + (lane & 3) * 2;
        *(float2*)(or1 + c) = make_float2(o[g][0], o[g][1]);
        *(float2*)(or2 + c) = make_float2(o[g][2], o[g][3]);
    }
}

// ---------------------------------------------------------------------------
extern "C" void kernel_launch(void* const* d_in, const int* in_sizes, int n_in,
                              void* d_out, int out_size)
{
    const float* x    = (const float*)d_in[0];
    const float* bias = (const float*)d_in[1];
    const int*   mask = (const int*)d_in[2];
    const float* wq   = (const float*)d_in[3];
    const float* bq   = (const float*)d_in[4];
    const float* wk   = (const float*)d_in[5];
    const float* bk   = (const float*)d_in[6];
    const float* wv   = (const float*)d_in[7];
    const float* bv   = (const float*)d_in[8];

    float* outp = (float*)d_out;                       // [2,16,2048,64]
    float* attn = outp + (size_t)BH * SEQ * HD;        // [2,16,2048,2048]

    cudaFuncSetAttribute(qkv_hmma_kernel,
                         cudaFuncAttributeMaxDynamicSharedMemorySize,
                         QKV_SMEM_BYTES);
    cudaFuncSetAttribute(attn_mma_kernel,
                         cudaFuncAttributeMaxDynamicSharedMemorySize,
                         ATTN_SMEM_BYTES);

    // 0a) round x / W to fp16
    split_src_kernel<<<dim3(2048, 4), 256>>>(x, wq, wk, wv);

    // 0b) premask + prescale bias (fp16)
    prep_bias_kernel<<<dim3(SEQ * SEQ / 2 / 256), 256>>>(bias, mask);

    // 1) QKV projections (single-term fp16 HMMA); q pre-scaled
    qkv_hmma_kernel<<<dim3(DM / 128, (BSZ * SEQ) / 128, 3), 256,
                      QKV_SMEM_BYTES>>>(bq, bk, bv);

    // 2) two-pass fp16 HMMA attention (normalized in-exponent)
    attn_mma_kernel<<<dim3(SEQ / 128, BH), 256, ATTN_SMEM_BYTES>>>(
        outp, attn);
}

// round 17
// speedup vs baseline: 1.0123x; 1.0123x over previous
#include <cuda_runtime.h>
#include <cuda_fp16.h>
#include <cstdint>

#define BSZ 2
#define NH 16
#define SEQ 2048
#define DM 1024
#define HD 64
#define BH (BSZ*NH)

// Scratch (device globals — no allocations allowed)
__device__ __half g_x16[BSZ*SEQ*DM];    // x (fp16)
__device__ __half g_w16[3*DM*DM];       // W (fp16)
__device__ __half g_q16[BH * SEQ * HD]; // q pre-scaled by 0.125*log2(e)
__device__ __half g_k16[BH * SEQ * HD];
__device__ __half g_v16[BH * SEQ * HD];
__device__ __half g_p16[(size_t)BH * SEQ * SEQ];   // unnormalized P scratch (fp16)
__device__ __half g_bmh[(size_t)NH * SEQ * SEQ];   // premasked bias*log2e (fp16)

#define LOG2E 1.44269504f
#define QSCALE (0.125f * LOG2E)
#define ONES2  0x3C003C00u      // half2(1.0, 1.0)
#define MASKV  (-60000.0f)      // fp16-safe "minus infinity" (exp2 -> 0)

// ---- helpers -----------------------------------------------------------------
__device__ __forceinline__ uint32_t h2bits(__half2 v) {
    return *reinterpret_cast<uint32_t*>(&v);
}
__device__ __forceinline__ uint32_t smem_u32(const void* p) {
    uint32_t a;
    asm("{ .reg .u64 t; cvta.to.shared.u64 t, %1; cvt.u32.u64 %0, t; }"
        : "=r"(a) : "l"(p));
    return a;
}
// 128B-row tiles: XOR 16B-chunk by (row&7)
__device__ __forceinline__ uint32_t swz_addr(uint32_t base, int row, int chunk) {
    uint32_t off = (uint32_t)(row * 128 + chunk * 16);
    return base + (off ^ ((off >> 3) & 0x70));
}
// 64B-row tiles: SW64 swizzle
__device__ __forceinline__ uint32_t swz64_addr(uint32_t base, int row, int chunk) {
    uint32_t off = (uint32_t)(row * 64 + chunk * 16);
    return base + (off ^ ((off >> 3) & 0x30));
}
__device__ __forceinline__ void ldsm_x4(uint32_t* r, uint32_t a) {
    asm volatile("ldmatrix.sync.aligned.m8n8.x4.shared.b16 {%0,%1,%2,%3}, [%4];"
        : "=r"(r[0]), "=r"(r[1]), "=r"(r[2]), "=r"(r[3]) : "r"(a));
}
__device__ __forceinline__ void ldsm_x4t(uint32_t* r, uint32_t a) {
    asm volatile("ldmatrix.sync.aligned.m8n8.x4.trans.shared.b16 {%0,%1,%2,%3}, [%4];"
        : "=r"(r[0]), "=r"(r[1]), "=r"(r[2]), "=r"(r[3]) : "r"(a));
}
__device__ __forceinline__ void mma_f16(float* d, const uint32_t* a,
                                        uint32_t b0, uint32_t b1) {
    asm volatile("mma.sync.aligned.m16n8k16.row.col.f32.f16.f16.f32 "
        "{%0,%1,%2,%3}, {%4,%5,%6,%7}, {%8,%9}, {%0,%1,%2,%3};"
        : "+f"(d[0]), "+f"(d[1]), "+f"(d[2]), "+f"(d[3])
        : "r"(a[0]), "r"(a[1]), "r"(a[2]), "r"(a[3]), "r"(b0), "r"(b1));
}
__device__ __forceinline__ void cp16(uint32_t dst, const void* src) {
    asm volatile("cp.async.cg.shared.global [%0], [%1], 16;"
                 :: "r"(dst), "l"(src) : "memory");
}
#define CP_COMMIT() asm volatile("cp.async.commit_group;" ::: "memory")
#define CP_WAIT1()  asm volatile("cp.async.wait_group 1;" ::: "memory")

// ---------------------------------------------------------------------------
// Kernel 0a: round x and W to fp16.
// ---------------------------------------------------------------------------
__global__ __launch_bounds__(256) void split_src_kernel(
    const float* __restrict__ x,
    const float* __restrict__ wq, const float* __restrict__ wk,
    const float* __restrict__ wv)
{
    const int z = blockIdx.y;
    const float* src = (z == 0) ? x : (z == 1) ? wq : (z == 2) ? wk : wv;
    uint32_t* dst = (z == 0) ? (uint32_t*)g_x16
                             : (uint32_t*)(g_w16 + (size_t)(z - 1) * DM * DM);
    const size_t n2 = (z == 0) ? (size_t)BSZ * SEQ * DM / 2
                               : (size_t)DM * DM / 2;
    for (size_t i = (size_t)blockIdx.x * 256 + threadIdx.x; i < n2;
         i += (size_t)gridDim.x * 256) {
        float2 v = ((const float2*)src)[i];
        dst[i] = h2bits(__floats2half2_rn(v.x, v.y));
    }
}

// ---------------------------------------------------------------------------
// Kernel 0b: premask + prescale bias to fp16: bm = mask ? bias*log2e : -60000.
// ---------------------------------------------------------------------------
__global__ __launch_bounds__(256) void prep_bias_kernel(
    const float* __restrict__ bias, const int* __restrict__ mask)
{
    const size_t i = (size_t)blockIdx.x * 256 + threadIdx.x;  // over SEQ*SEQ/2
    int2 m = ((const int2*)mask)[i];
    #pragma unroll 4
    for (int h = 0; h < NH; h++) {
        float2 bv = ((const float2*)(bias + (size_t)h * SEQ * SEQ))[i];
        float ox = m.x ? bv.x * LOG2E : MASKV;
        float oy = m.y ? bv.y * LOG2E : MASKV;
        ((uint32_t*)(g_bmh + (size_t)h * SEQ * SEQ))[i] =
            h2bits(__floats2half2_rn(ox, oy));
    }
}

// ---------------------------------------------------------------------------
// Kernel 1: QKV projection via single-term fp16 HMMA.
// 128x128 tile, K-slab 32, 64B-row smem (SW64), double-buffered, 2 CTAs/SM.
// Q output pre-scaled by 0.125*log2e.
// ---------------------------------------------------------------------------
#define QKV_SMEM_BYTES 32768     // 2 stages x (x 8K | w 8K)

__global__ __launch_bounds__(256, 2) void qkv_hmma_kernel(
    const float* __restrict__ bq, const float* __restrict__ bk,
    const float* __restrict__ bv)
{
    extern __shared__ char smem[];
    const uint32_t sb = smem_u32(smem);
    const int tid = threadIdx.x, wid = tid >> 5, lane = tid & 31;
    const int z = blockIdx.z;
    const float* bvec = (z == 0) ? bq : (z == 1) ? bk : bv;
    __half* outp = (z == 0) ? g_q16 : (z == 1) ? g_k16 : g_v16;
    const __half* W = g_w16 + (size_t)z * DM * DM;
    const float oscale = (z == 0) ? QSCALE : 1.0f;
    const int col0 = blockIdx.x << 7;
    const int row0 = blockIdx.y << 7;

    auto issue = [&](int slab, int buf) {
        const int k0 = slab << 5;
        const uint32_t base = sb + (uint32_t)buf * 16384;
        #pragma unroll
        for (int it = 0; it < 2; it++) {
            const int idx = tid + it * 256;     // 0..511
            const int r = idx >> 2, c = idx & 3;
            uint32_t off = (uint32_t)(r * 64 + c * 16);
            off ^= (off >> 3) & 0x30;
            const size_t gx = (size_t)(row0 + r) * DM + k0 + c * 8;
            const size_t gw = (size_t)(col0 + r) * DM + k0 + c * 8;
            cp16(base + off,        g_x16 + gx);
            cp16(base + 8192 + off, W + gw);
        }
    };

    float s[16][4];
    #pragma unroll
    for (int g = 0; g < 16; g++)
        #pragma unroll
        for (int j = 0; j < 4; j++) s[g][j] = 0.0f;

    issue(0, 0);
    CP_COMMIT();

    for (int kt = 0; kt < 32; kt++) {
        if (kt) __syncthreads();
        if (kt < 31) issue(kt + 1, (kt + 1) & 1);
        CP_COMMIT();
        CP_WAIT1();
        __syncthreads();

        const uint32_t base = sb + (uint32_t)(kt & 1) * 16384;
        const int rA = (wid << 4) + (lane & 7) + ((lane >> 3) & 1) * 8;
        uint32_t ah[2][4];
        #pragma unroll
        for (int ks = 0; ks < 2; ks++) {
            const int ch = ks * 2 + (lane >> 4);
            ldsm_x4(ah[ks], swz64_addr(base, rA, ch));
        }
        #pragma unroll
        for (int nf = 0; nf < 8; nf++) {
            const int rB = nf * 16 + (lane & 7) + (lane >> 4) * 8;
            #pragma unroll
            for (int ks = 0; ks < 2; ks++) {
                const int ch = ks * 2 + ((lane >> 3) & 1);
                uint32_t w4[4];
                ldsm_x4(w4, swz64_addr(base + 8192, rB, ch));
                mma_f16(s[2*nf],   ah[ks], w4[0], w4[1]);
                mma_f16(s[2*nf+1], ah[ks], w4[2], w4[3]);
            }
        }
    }

    // epilogue: + bias (then optional q pre-scale); store fp16, head-split
    const int r1 = row0 + (wid << 4) + (lane >> 2);
    const int r2 = r1 + 8;
    const int bb1 = r1 >> 11, ss1 = r1 & (SEQ - 1);
    const int bb2 = r2 >> 11, ss2 = r2 & (SEQ - 1);
    #pragma unroll
    for (int g = 0; g < 16; g++) {
        const int c = col0 + g * 8 + (lane & 3) * 2;
        const int h = c >> 6, d = c & 63;
        float2 b2 = *(const float2*)(bvec + c);
        const size_t e1 = (((size_t)bb1 * NH + h) * SEQ + ss1) * HD + d;
        const size_t e2 = (((size_t)bb2 * NH + h) * SEQ + ss2) * HD + d;
        *(uint32_t*)&outp[e1] = h2bits(__floats2half2_rn(
            (s[g][0] + b2.x) * oscale, (s[g][1] + b2.y) * oscale));
        *(uint32_t*)&outp[e2] = h2bits(__floats2half2_rn(
            (s[g][2] + b2.x) * oscale, (s[g][3] + b2.y) * oscale));
    }
}

// ---------------------------------------------------------------------------
// Kernel 2: fp16 HMMA attention (single pass, R15 structure).
// p = h2exp2(hadd2(f16x2(s), bm)) — all-fp16 epilogue, 1 MUFU per 2 elems.
// P tile staged in XOR-swizzled smem -> coalesced STG.128 to fp16 scratch.
// Rowsum via ones-MMA. Fused rescale reads scratch, writes fp32 attn.
// blockIdx.y = h*2 + b so batch-pair CTAs share bm rows in L2.
// ---------------------------------------------------------------------------
#define SM_Q  0
#define SM_P  16384
#define SM_ST 32768
#define STAGE_BYTES 34816      // K 8192 | V 8192 | BM 18432 (128 rows x 144B)
#define BM_OFF 16384
#define ATTN_SMEM_BYTES (32768 + 2*34816)

__global__ __launch_bounds__(256, 2) void attn_mma_kernel(
    float* __restrict__ outp,
    float* __restrict__ attn)
{
    extern __shared__ char smem[];
    const uint32_t sb = smem_u32(smem);

    const int tid = threadIdx.x;
    const int wid = tid >> 5, lane = tid & 31;
    const int h  = blockIdx.y >> 1;            // bias row set
    const int b  = blockIdx.y & 1;             // batch
    const int bh = b * NH + h;
    const int q0 = blockIdx.x << 7;
    const size_t bhbase = (size_t)bh * SEQ;
    const __half* bmbase = g_bmh + ((size_t)h * SEQ + q0) * SEQ;

    auto issue_kv = [&](int kt, int buf) {
        const int k0 = kt << 6;
        const uint32_t base = sb + SM_ST + (uint32_t)buf * STAGE_BYTES;
        const char* kk = (const char*)(g_k16 + (bhbase + k0) * HD);
        const char* vv = (const char*)(g_v16 + (bhbase + k0) * HD);
        #pragma unroll
        for (int it = 0; it < 2; it++) {
            const int idx = tid + it * 256;     // 0..511
            const uint32_t off = (uint32_t)(idx << 4);
            const uint32_t dst = off ^ ((off >> 3) & 0x70);
            cp16(base + dst,        kk + off);
            cp16(base + 8192 + dst, vv + off);
        }
        // bm block: 128 q-rows x 64 k (fp16), 8 chunks/row, 144B row stride
        #pragma unroll
        for (int it = 0; it < 4; it++) {
            const int idx = tid + it * 256;     // 0..1023
            const int r = idx >> 3, c = idx & 7;
            cp16(base + BM_OFF + (uint32_t)(r * 144 + c * 16),
                 bmbase + (size_t)r * SEQ + k0 + c * 8);
        }
    };

    // prologue: Q tile (128x64 fp16 = 16KB) + stage(0)
    {
        const char* qq = (const char*)(g_q16 + (bhbase + q0) * HD);
        #pragma unroll
        for (int it = 0; it < 4; it++) {
            const int idx = tid + it * 256;     // 0..1023
            const uint32_t off = (uint32_t)(idx << 4);
            const uint32_t dst = off ^ ((off >> 3) & 0x70);
            cp16(sb + SM_Q + dst, qq + off);
        }
    }
    issue_kv(0, 0);
    CP_COMMIT();

    float o[8][4];
    #pragma unroll
    for (int g = 0; g < 8; g++)
        #pragma unroll
        for (int j = 0; j < 4; j++) o[g][j] = 0.0f;
    float racc[4] = {0.0f, 0.0f, 0.0f, 0.0f};   // ones-MMA rowsum accumulator

    const int r1 = (wid << 4) + (lane >> 2);
    const int qg1 = q0 + r1, qg2 = qg1 + 8;

    const int rA = (wid << 4) + (lane & 7) + ((lane >> 3) & 1) * 8;
    const int bmo1 = r1 * 144 + (lane & 3) * 4;        // byte offsets in bm block
    const int bmo2 = (r1 + 8) * 144 + (lane & 3) * 4;
    // P staging: XOR-swizzled 128B rows; same swizzle sel for r1 and r1+8
    const int psw = (lane >> 2) & 7;
    const uint32_t po1 = (uint32_t)(SM_P + r1 * 128 + (lane & 3) * 4);
    const uint32_t po2 = po1 + 8 * 128;

    for (int kt = 0; kt < SEQ / 64; kt++) {
        const int k0 = kt << 6;
        if (kt) __syncthreads();               // stage + P-smem free
        if (kt < SEQ / 64 - 1) issue_kv(kt + 1, (kt + 1) & 1);
        CP_COMMIT();
        CP_WAIT1();
        __syncthreads();

        const uint32_t base = sb + SM_ST + (uint32_t)(kt & 1) * STAGE_BYTES;
        const char* bmst = smem + SM_ST + (size_t)(kt & 1) * STAGE_BYTES + BM_OFF;

        // ---- S' = Q' K^T over 64 cols (already scaled by 0.125*log2e) ----
        float s[8][4];
        #pragma unroll
        for (int g = 0; g < 8; g++)
            #pragma unroll
            for (int j = 0; j < 4; j++) s[g][j] = 0.0f;

        #pragma unroll
        for (int ks = 0; ks < 4; ks++) {
            uint32_t qf[4];
            ldsm_x4(qf, swz_addr(sb + SM_Q, rA, ks * 2 + (lane >> 4)));
            #pragma unroll
            for (int nf = 0; nf < 4; nf++) {
                const int rB = nf * 16 + (lane & 7) + (lane >> 4) * 8;
                uint32_t k4[4];
                ldsm_x4(k4, swz_addr(base, rB, ks * 2 + ((lane >> 3) & 1)));
                mma_f16(s[2*nf],   qf, k4[0], k4[1]);
                mma_f16(s[2*nf+1], qf, k4[2], k4[3]);
            }
        }

        // ---- all-fp16 epilogue: p = exp2(f16(s) + bm); smem + frags ----
        uint32_t ph[4][4];
        #pragma unroll
        for (int g = 0; g < 8; g++) {
            __half2 bA = *(const __half2*)(bmst + bmo1 + g * 16);
            __half2 bB = *(const __half2*)(bmst + bmo2 + g * 16);
            __half2 pA = h2exp2(__hadd2(__floats2half2_rn(s[g][0], s[g][1]), bA));
            __half2 pB = h2exp2(__hadd2(__floats2half2_rn(s[g][2], s[g][3]), bB));
            const uint32_t h01 = h2bits(pA);
            const uint32_t h23 = h2bits(pB);
            const uint32_t go = (uint32_t)((g ^ psw) << 4);
            *(uint32_t*)(smem + po1 + go) = h01;
            *(uint32_t*)(smem + po2 + go) = h23;
            const int ks = g >> 1, ix = (g & 1) * 2;
            ph[ks][ix + 0] = h01;
            ph[ks][ix + 1] = h23;
        }

        // ---- O += P V; rowsum += P x ones (tensor pipe) ----
        #pragma unroll
        for (int ks = 0; ks < 4; ks++) {
            mma_f16(racc, ph[ks], ONES2, ONES2);
            const int rV = ks * 16 + (lane & 7) + ((lane >> 3) & 1) * 8;
            #pragma unroll
            for (int dg = 0; dg < 4; dg++) {
                uint32_t v4[4];
                ldsm_x4t(v4, swz_addr(base + 8192, rV, 2 * dg + (lane >> 4)));
                mma_f16(o[2*dg],   ph[ks], v4[0], v4[1]);
                mma_f16(o[2*dg+1], ph[ks], v4[2], v4[3]);
            }
        }

        // ---- coalesced P tile store: smem -> g_p16 (STG.128) ----
        __syncthreads();
        #pragma unroll
        for (int it = 0; it < 4; it++) {
            const int idx = tid + it * 256;    // 0..1023 chunks of 16B
            const int r = idx >> 3, c = idx & 7;
            uint4 v = *(const uint4*)(smem + SM_P + r * 128 + ((c ^ (r & 7)) << 4));
            *(uint4*)(g_p16 + (bhbase + q0 + r) * SEQ + k0 + c * 8) = v;
        }
    }

    // ---- rowsums come straight from the ones-MMA accumulator ----
    const float inv1 = 1.0f / racc[0];
    const float inv2 = 1.0f / racc[2];

    // normalized O
    float* or1 = outp + (bhbase + qg1) * HD;
    float* or2 = outp + (bhbase + qg2) * HD;
    #pragma unroll
    for (int g = 0; g < 8; g++) {
        const int c = g * 8 + (lane & 3) * 2;
        *(float2*)(or1 + c) = make_float2(o[g][0] * inv1, o[g][1] * inv1);
        *(float2*)(or2 + c) = make_float2(o[g][2] * inv2, o[g][3] * inv2);
    }

    // ---- fused rescale: read fp16 P scratch, write fp32 normalized attn ----
    float* rs = (float*)smem;          // 128 floats; stage smem no longer needed
    __syncthreads();                   // P stores done; smem free
    if ((lane & 3) == 0) {
        rs[r1] = inv1;
        rs[qg2 - q0] = inv2;
    }
    __syncthreads();
    #pragma unroll 1
    for (int rr = 0; rr < 16; rr++) {
        const int qr = (wid << 4) + rr;
        const float inv = rs[qr];
        const uint4* src = (const uint4*)(g_p16 + (bhbase + q0 + qr) * SEQ);
        float4* dst = (float4*)(attn + (bhbase + q0 + qr) * SEQ);
        #pragma unroll 2
        for (int c = lane; c < SEQ / 8; c += 32) {   // 8 halfs per uint4
            uint4 hv = src[c];
            const __half2* hp = (const __half2*)&hv;
            float2 f0 = __half22float2(hp[0]);
            float2 f1 = __half22float2(hp[1]);
            float2 f2 = __half22float2(hp[2]);
            float2 f3 = __half22float2(hp[3]);
            dst[c*2+0] = make_float4(f0.x*inv, f0.y*inv, f1.x*inv, f1.y*inv);
            dst[c*2+1] = make_float4(f2.x*inv, f2.y*inv, f3.x*inv, f3.y*inv);
        }
    }
}

// ---------------------------------------------------------------------------
extern "C" void kernel_launch(void* const* d_in, const int* in_sizes, int n_in,
                              void* d_out, int out_size)
{
    const float* x    = (const float*)d_in[0];
    const float* bias = (const float*)d_in[1];
    const int*   mask = (const int*)d_in[2];
    const float* wq   = (const float*)d_in[3];
    const float* bq   = (const float*)d_in[4];
    const float* wk   = (const float*)d_in[5];
    const float* bk   = (const float*)d_in[6];
    const float* wv   = (const float*)d_in[7];
    const float* bv   = (const float*)d_in[8];

    float* outp = (float*)d_out;                       // [2,16,2048,64]
    float* attn = outp + (size_t)BH * SEQ * HD;        // [2,16,2048,2048]

    cudaFuncSetAttribute(qkv_hmma_kernel,
                         cudaFuncAttributeMaxDynamicSharedMemorySize,
                         QKV_SMEM_BYTES);
    cudaFuncSetAttribute(attn_mma_kernel,
                         cudaFuncAttributeMaxDynamicSharedMemorySize,
                         ATTN_SMEM_BYTES);

    // 0a) round x / W to fp16
    split_src_kernel<<<dim3(2048, 4), 256>>>(x, wq, wk, wv);

    // 0b) premask + prescale bias (fp16)
    prep_bias_kernel<<<dim3(SEQ * SEQ / 2 / 256), 256>>>(bias, mask);

    // 1) QKV projections (single-term fp16 HMMA); q pre-scaled
    qkv_hmma_kernel<<<dim3(DM / 128, (BSZ * SEQ) / 128, 3), 256,
                      QKV_SMEM_BYTES>>>(bq, bk, bv);

    // 2) fp16 HMMA attention (single pass) + fused rescale
    attn_mma_kernel<<<dim3(SEQ / 128, BH), 256, ATTN_SMEM_BYTES>>>(
        outp, attn);
}